// round 9
// baseline (speedup 1.0000x reference)
#include <cuda_runtime.h>

// Problem constants (fixed by the reference):
// B=1, C=8, O=8, G=12, X=12, CH=8, CW=40, Xo=Yo=Zo=9
#define HWN   320      // CH*CW
#define OBN   56       // O*7  (ob = o*7+b)
#define KKN   216      // C*27
#define KH    108      // k-half
#define WH    (KH*OBN) // 6048 floats per W half
#define GON   96       // G*O
#define VOX   1728     // 12*12*12
#define OSTRIDE (VOX*HWN)   // 552960, stride of one (g,o) plane

typedef unsigned long long ull;

__device__ __forceinline__ ull fma2(ull a, ull b, ull c) {
    ull d; asm("fma.rn.f32x2 %0, %1, %2, %3;" : "=l"(d) : "l"(a), "l"(b), "l"(c)); return d;
}
__device__ __forceinline__ ull pack2(float lo, float hi) {
    ull d; asm("mov.b64 %0, {%1, %2};" : "=l"(d) : "f"(lo), "f"(hi)); return d;
}
__device__ __forceinline__ void unpack2(ull v, float& lo, float& hi) {
    asm("mov.b64 {%0, %1}, %2;" : "=f"(lo), "=f"(hi) : "l"(v));
}

// ---------------------------------------------------------------------------
// Fused kernel: one block per output voxel (1728).
//  * Border voxels: zero their 96x320 slab, exit.
//  * Interior voxels (n = 729 of them):
//    Stage A (GEMM): Q[ob,hw] = sum_k W[ob,k] * X[k,hw], thread = 28 ob x 2 hw,
//      W staged in two 108-k halves (24.2 KB each) so total smem = 96.8 KB
//      -> 2 CTAs/SM. Q written to smem, split QsA (o0-3) / QsB (o4-7) with
//      16-B pos stride so stage-B tap reads are conflict-free LDS.128.
//    Stage B: thread = hw; full 12g x 8o stack at clamped (ii,jj); T-gather is
//      a static output-index rotation; bias index = o folds into acc init.
// ---------------------------------------------------------------------------
extern "C" __global__ void __launch_bounds__(320, 2)
fused_kernel(const float* __restrict__ x,
             const float* __restrict__ weight,
             const float* __restrict__ bias,
             const float* __restrict__ basis,
             const int*   __restrict__ Iin,
             const int*   __restrict__ Jin,
             const int*   __restrict__ Tin,
             float*       __restrict__ out)
{
    extern __shared__ float sm[];
    float* QsA    = sm;                        // 7*320*4 = 8960 floats (o0..3)
    float* QsB    = QsA + 8960;                // 8960 floats (o4..7)
    float* w_h    = QsB + 8960;                // 6048 floats (one W half)
    int*   rowoff = (int*)(w_h + WH);          // 218 ints
    float* bsum   = (float*)(rowoff + KKN + 2);// 8 floats
    ull*   basP   = (ull*)w_h;                 // overlays w_h after stage A

    const int v   = blockIdx.x;
    const int tid = threadIdx.x;
    const int xx = v / 144, yy = (v / 12) % 12, zz = v % 12;
    const bool interior = (xx >= 1 && xx <= 9 && yy >= 1 && yy <= 9 && zz >= 1 && zz <= 9);

    if (!interior) {
        // Zero the 96 (g,o)-planes of this voxel: coalesced float4.
        float4* out4 = (float4*)out;
        const size_t base4 = (size_t)v * (HWN / 4);
        for (int i = tid; i < GON * (HWN / 4); i += 320) {
            int go = i / (HWN / 4), q = i % (HWN / 4);
            out4[(size_t)go * (OSTRIDE / 4) + base4 + q] = make_float4(0.f, 0.f, 0.f, 0.f);
        }
        return;
    }

    // ---------------- Stage A: per-n GEMM into smem Q ----------------
    const int xi = xx - 1, yj = yy - 1, zk = zz - 1;
    for (int k = tid; k < KKN + 2; k += 320) {
        int kc = (k < KKN) ? k : (KKN - 1);
        int c = kc / 27, f = kc % 27;
        int fi = f / 9, fj = (f / 3) % 3, fk = f % 3;
        rowoff[k] = (((c * 12 + xi + fi) * 12 + (yj + fj)) * 12 + (zk + fk)) * HWN;
    }

    const int obh = tid / 160;         // 0/1, uniform per warp (160 = 5 warps)
    const int hwb = (tid % 160) * 2;   // hw base; warp = 256B contiguous LDG.64

    ull acc[14][2];                    // [ob-pair j][hw p]
    #pragma unroll
    for (int j = 0; j < 14; j++) { acc[j][0] = 0ULL; acc[j][1] = 0ULL; }

    float2 p0, p1;
    #pragma unroll 1
    for (int kh = 0; kh < 2; kh++) {
        __syncthreads();   // rowoff ready (kh=0) / previous half consumed (kh=1)
        // Load W half: weight[o][c][f][b] -> w_h[kl*56 + obh*28 + obl]
        for (int i = tid; i < WH; i += 320) {
            int kl = i / OBN, ob = i % OBN;
            int kg = kh * KH + kl;
            int c = kg / 27, f = kg % 27;
            int o = ob / 7,  b = ob % 7;
            int oh = ob / 28, obl = ob % 28;
            w_h[kl * OBN + oh * 28 + obl] = weight[((o * 8 + c) * 27 + f) * 7 + b];
        }
        __syncthreads();
        if (kh == 0) {
            p0 = __ldg((const float2*)(x + rowoff[0] + hwb));
            p1 = __ldg((const float2*)(x + rowoff[1] + hwb));
        }
        #pragma unroll 1
        for (int kl = 0; kl < KH; kl++) {
            int kg = kh * KH + kl;
            float2 pn = __ldg((const float2*)(x + rowoff[kg + 2] + hwb));
            ull xs0 = pack2(p0.x, p0.x), xs1 = pack2(p0.y, p0.y);
            const ulonglong2* wp = (const ulonglong2*)(w_h + kl * OBN + obh * 28);
            #pragma unroll
            for (int j = 0; j < 7; j++) {
                ulonglong2 w2 = wp[j];                 // LDS.128 broadcast
                acc[2 * j    ][0] = fma2(w2.x, xs0, acc[2 * j    ][0]);
                acc[2 * j    ][1] = fma2(w2.x, xs1, acc[2 * j    ][1]);
                acc[2 * j + 1][0] = fma2(w2.y, xs0, acc[2 * j + 1][0]);
                acc[2 * j + 1][1] = fma2(w2.y, xs1, acc[2 * j + 1][1]);
            }
            p0 = p1; p1 = pn;
        }
    }

    // Unpack and store Q to smem: half obh -> QsA/QsB, [b*320+hw]*4 + ol.
    {
        float accf[28][2];
        #pragma unroll
        for (int j = 0; j < 14; j++) {
            unpack2(acc[j][0], accf[2 * j][0], accf[2 * j + 1][0]);
            unpack2(acc[j][1], accf[2 * j][1], accf[2 * j + 1][1]);
        }
        float* qdst = obh ? QsB : QsA;
        #pragma unroll
        for (int b = 0; b < 7; b++) {
            #pragma unroll
            for (int p = 0; p < 2; p++) {
                float4 v4 = make_float4(accf[b][p], accf[7 + b][p],
                                        accf[14 + b][p], accf[21 + b][p]);
                *reinterpret_cast<float4*>(qdst + (b * HWN + hwb + p) * 4) = v4;
            }
        }
    }
    __syncthreads();

    // basP overlays w_h: basis[g][b][u][v] -> basP[(b*9+uv)*12 + g], duplicated.
    for (int i = tid; i < 756; i += 320) {
        float val = basis[i];
        int g = i / 63, k = i % 63;
        basP[k * 12 + g] = pack2(val, val);
    }
    if (tid < 8) {
        // bias_basis = tile(arange(O), G) -> bias index is o.
        float s = 0.f;
        for (int i = 0; i < 27; i++) s += bias[tid * 27 + i];
        bsum[tid] = s;
    }
    __syncthreads();

    // ---------------- Stage B: basis contraction + gather + store ----------------
    const int ii = __ldg(Iin + tid) - 1;          // in [0,5]
    const int jj = __ldg(Jin + tid) - 1;          // in [0,37]
    const bool border = (__ldg(Tin + tid) != 0);  // T[g=0]: 1 on border, 0 inside
    const int pbase = ii * 40 + jj;

    ull binit[4];
    #pragma unroll
    for (int p = 0; p < 4; p++) binit[p] = pack2(bsum[2 * p], bsum[2 * p + 1]);

    float* obase = out + (size_t)v * HWN + tid;

    #pragma unroll 1
    for (int gh = 0; gh < 2; gh++) {
        ull acc2[6][4];
        #pragma unroll
        for (int g = 0; g < 6; g++)
            #pragma unroll
            for (int p = 0; p < 4; p++) acc2[g][p] = binit[p];

        #pragma unroll 1
        for (int b = 0; b < 7; b++) {
            const float* qa = QsA + b * (HWN * 4);
            const float* qb = QsB + b * (HWN * 4);
            const ull*   bp = basP + b * 108 + gh * 6;   // b*9*12
            #pragma unroll
            for (int uv = 0; uv < 9; uv++) {
                int u = uv / 3, vv = uv - u * 3;
                int pos = pbase + u * 40 + vv;
                ulonglong2 qA = *(const ulonglong2*)(qa + pos * 4);  // o(0,1),(2,3)
                ulonglong2 qB = *(const ulonglong2*)(qb + pos * 4);  // o(4,5),(6,7)
                const ull* bk = bp + uv * 12;
                #pragma unroll
                for (int g = 0; g < 6; g++) {
                    ull bv = bk[g];      // LDS.64 broadcast (pre-duplicated)
                    acc2[g][0] = fma2(qA.x, bv, acc2[g][0]);
                    acc2[g][1] = fma2(qA.y, bv, acc2[g][1]);
                    acc2[g][2] = fma2(qB.x, bv, acc2[g][2]);
                    acc2[g][3] = fma2(qB.y, bv, acc2[g][3]);
                }
            }
        }
        // Group t lands at output g = t (interior) or (t+11)%12 (border).
        #pragma unroll
        for (int g = 0; g < 6; g++) {
            int t = gh * 6 + g;
            int gout = border ? (t == 0 ? 11 : t - 1) : t;
            float* ob8 = obase + (size_t)(gout * 8) * OSTRIDE;
            #pragma unroll
            for (int p = 0; p < 4; p++) {
                float lo, hi; unpack2(acc2[g][p], lo, hi);
                ob8[(size_t)(2 * p)     * OSTRIDE] = lo;
                ob8[(size_t)(2 * p + 1) * OSTRIDE] = hi;
            }
        }
    }
}

// ---------------------------------------------------------------------------
extern "C" void kernel_launch(void* const* d_in, const int* in_sizes, int n_in,
                              void* d_out, int out_size)
{
    const float* x      = (const float*)d_in[0];
    const float* weight = (const float*)d_in[1];
    const float* bias   = (const float*)d_in[2];
    const float* basis  = (const float*)d_in[3];
    const int*   I      = (const int*)d_in[4];
    const int*   J      = (const int*)d_in[5];
    const int*   T      = (const int*)d_in[6];
    float*       out    = (float*)d_out;

    // 8960 + 8960 + 6048 floats + 218 ints + 8 floats = 24194 floats
    const int smem = (8960 + 8960 + WH + 8) * 4 + (KKN + 2) * 4;   // 96776 B
    cudaFuncSetAttribute(fused_kernel, cudaFuncAttributeMaxDynamicSharedMemorySize, smem);

    fused_kernel<<<VOX, 320, smem>>>(x, weight, bias, basis, I, J, T, out);
}

// round 14
// speedup vs baseline: 1.1422x; 1.1422x over previous
#include <cuda_runtime.h>

// Problem constants (fixed by the reference):
// B=1, C=8, O=8, G=12, X=12, CH=8, CW=40, Xo=Yo=Zo=9
#define HWN   320      // CH*CW
#define NB    729      // 9*9*9 interior voxels
#define OBN   56       // O*7  (ob = o*7+b)
#define KKN   216      // C*27
#define GON   96       // G*O
#define VOX   1728     // 12*12*12
#define OSTRIDE (VOX*HWN)         // 552960, stride of one (g,o) plane
#define QHALF (7*HWN*4)           // 8960 floats: one o-half plane per n
#define QTILE (2*QHALF)           // 17920 floats per n
#define WSTRIDE 64                // padded k-stride in w_s (floats)

typedef unsigned long long ull;

__device__ __forceinline__ ull fma2(ull a, ull b, ull c) {
    ull d; asm("fma.rn.f32x2 %0, %1, %2, %3;" : "=l"(d) : "l"(a), "l"(b), "l"(c)); return d;
}
__device__ __forceinline__ ull pack2(float lo, float hi) {
    ull d; asm("mov.b64 %0, {%1, %2};" : "=l"(d) : "f"(lo), "f"(hi)); return d;
}
__device__ __forceinline__ void unpack2(ull v, float& lo, float& hi) {
    asm("mov.b64 {%0, %1}, %2;" : "=f"(lo), "=f"(hi) : "l"(v));
}

// Scratch: per n, two split planes:
//   QA[n][b*320+hw][o0..3] at offset 0, QB[n][b*320+hw][o4..7] at offset QHALF.
// 16-B pos stride so stage2 tap reads are conflict-free LDS.128.
__device__ __align__(16) float g_Q[NB * QTILE];

// ---------------------------------------------------------------------------
// Stage 1: register-tiled GEMM  Q[ob, hw] = sum_k W[ob,k] * X[k, hw]  per n.
// Thread shape: 28 ob x 2 hw. Block 320 = obh(2) x hwp(160); warp-uniform obh.
// Per k: 7 LDS.128 (bcast W pairs) + 1 LDG.64 (x, coalesced) + 28 FFMA2.
// ---------------------------------------------------------------------------
extern "C" __global__ void __launch_bounds__(320, 2)
stage1_kernel(const float* __restrict__ x, const float* __restrict__ weight)
{
    extern __shared__ float sm1[];
    float* w_s    = sm1;                          // KKN*WSTRIDE floats (padded)
    int*   rowoff = (int*)(w_s + KKN * WSTRIDE);  // KKN+2 ints

    const int n   = blockIdx.x;
    const int tid = threadIdx.x;

    // weight[o][c][f][b] -> w_s[k*64 + obh*32 + (ob%28)], k = c*27+f, ob = o*7+b
    for (int idx = tid; idx < KKN * OBN; idx += 320) {
        int k = idx / OBN, ob = idx % OBN;
        int c = k / 27,    f  = k % 27;
        int o = ob / 7,    b  = ob % 7;
        int obh = ob / 28, obl = ob % 28;
        w_s[k * WSTRIDE + obh * 32 + obl] = weight[((o * 8 + c) * 27 + f) * 7 + b];
    }
    const int xi = n / 81, yj = (n / 9) % 9, zk = n % 9;
    for (int k = tid; k < KKN + 2; k += 320) {
        int kc = (k < KKN) ? k : (KKN - 1);
        int c = kc / 27, f = kc % 27;
        int fi = f / 9, fj = (f / 3) % 3, fk = f % 3;
        rowoff[k] = (((c * 12 + xi + fi) * 12 + (yj + fj)) * 12 + (zk + fk)) * HWN;
    }
    __syncthreads();

    const int obh = tid / 160;         // 0/1, uniform per warp (160 = 5 warps)
    const int hwb = (tid % 160) * 2;   // hw base, warp = 256B contiguous LDG.64

    ull acc[14][2];                    // [pair j][hw p]
    #pragma unroll
    for (int j = 0; j < 14; j++) { acc[j][0] = 0ULL; acc[j][1] = 0ULL; }

    float2 p0 = __ldg((const float2*)(x + rowoff[0] + hwb));
    float2 p1 = __ldg((const float2*)(x + rowoff[1] + hwb));
    for (int k = 0; k < KKN; k++) {
        float2 pn = __ldg((const float2*)(x + rowoff[k + 2] + hwb));
        ull xs0 = pack2(p0.x, p0.x), xs1 = pack2(p0.y, p0.y);
        const ulonglong2* wp = (const ulonglong2*)(w_s + k * WSTRIDE + obh * 32);
        #pragma unroll
        for (int j = 0; j < 7; j++) {
            ulonglong2 w2 = wp[j];                     // LDS.128 broadcast
            acc[2 * j    ][0] = fma2(w2.x, xs0, acc[2 * j    ][0]);
            acc[2 * j    ][1] = fma2(w2.x, xs1, acc[2 * j    ][1]);
            acc[2 * j + 1][0] = fma2(w2.y, xs0, acc[2 * j + 1][0]);
            acc[2 * j + 1][1] = fma2(w2.y, xs1, acc[2 * j + 1][1]);
        }
        p0 = p1; p1 = pn;
    }

    float accf[28][2];
    #pragma unroll
    for (int j = 0; j < 14; j++) {
        unpack2(acc[j][0], accf[2 * j][0], accf[2 * j + 1][0]);
        unpack2(acc[j][1], accf[2 * j][1], accf[2 * j + 1][1]);
    }

    // Store split: half obh -> plane at obh*QHALF, [(b*320+hw)*4 + ol].
    float* qn = g_Q + (size_t)n * QTILE + obh * QHALF;
    #pragma unroll
    for (int b = 0; b < 7; b++) {
        #pragma unroll
        for (int p = 0; p < 2; p++) {
            float4 v = make_float4(accf[b][p], accf[7 + b][p],
                                   accf[14 + b][p], accf[21 + b][p]);
            *reinterpret_cast<float4*>(qn + (b * HWN + hwb + p) * 4) = v;
        }
    }
}

// ---------------------------------------------------------------------------
// Stage 2 (direct-write + border zero): one block per output voxel.
// Border voxels: zero the 96x320 slab. Interior: thread = hw; compute the
// full 12g x 8o stack at clamped (ii,jj); T-gather is a static output-index
// rotation (T[g] = g interior, (g+1)%12 border); bias index = o.
// Q taps: two conflict-free LDS.128 from the split QsA/QsB planes.
// ---------------------------------------------------------------------------
extern "C" __global__ void __launch_bounds__(320, 2)
stage2_kernel(const float* __restrict__ bias,
              const float* __restrict__ basis,
              const int*   __restrict__ Iin,
              const int*   __restrict__ Jin,
              const int*   __restrict__ Tin,
              float*       __restrict__ out)
{
    extern __shared__ char sm2raw[];
    ull*   basP = (ull*)sm2raw;                  // [k=63][g=12] duplicated pairs
    float* QsA  = (float*)(basP + 756);          // 8960 floats (o0..3)
    float* QsB  = QsA + QHALF;                   // 8960 floats (o4..7)
    float* bsum = QsB + QHALF;                   // 8

    const int v   = blockIdx.x;                  // voxel 0..1727
    const int tid = threadIdx.x;
    const int xx = v / 144, yy = (v / 12) % 12, zz = v % 12;
    const bool interior = (xx >= 1 && xx <= 9 && yy >= 1 && yy <= 9 && zz >= 1 && zz <= 9);

    if (!interior) {
        // Zero the 96 (g,o)-planes of this voxel: coalesced float4.
        float4* out4 = (float4*)out;
        const size_t base4 = (size_t)v * (HWN / 4);
        for (int i = tid; i < GON * (HWN / 4); i += 320) {
            int go = i / (HWN / 4), q = i % (HWN / 4);
            out4[(size_t)go * (OSTRIDE / 4) + base4 + q] = make_float4(0.f, 0.f, 0.f, 0.f);
        }
        return;
    }

    const int n = (xx - 1) * 81 + (yy - 1) * 9 + (zz - 1);

    {
        const float4* src = (const float4*)(g_Q + (size_t)n * QTILE);
        float4* dst = (float4*)QsA;   // QsA and QsB are contiguous
        for (int i = tid; i < QTILE / 4; i += 320) dst[i] = src[i];
    }
    // basis[g][b][u][v] -> basP[(b*9+uv)*12 + g], duplicated into both halves.
    for (int i = tid; i < 756; i += 320) {
        float val = basis[i];
        int g = i / 63, k = i % 63;
        basP[k * 12 + g] = pack2(val, val);
    }
    if (tid < 8) {
        // bias_basis = tile(arange(O), G) -> bias index is o.
        float s = 0.f;
        for (int i = 0; i < 27; i++) s += bias[tid * 27 + i];
        bsum[tid] = s;
    }
    __syncthreads();

    const int ii = __ldg(Iin + tid) - 1;          // in [0,5]
    const int jj = __ldg(Jin + tid) - 1;          // in [0,37]
    const bool border = (__ldg(Tin + tid) != 0);  // T[g=0]: 1 on border, 0 inside
    const int pbase = ii * 40 + jj;

    ull binit[4];
    #pragma unroll
    for (int p = 0; p < 4; p++) binit[p] = pack2(bsum[2 * p], bsum[2 * p + 1]);

    float* obase = out + (size_t)v * HWN + tid;

    #pragma unroll 1
    for (int gh = 0; gh < 2; gh++) {
        ull acc[6][4];
        #pragma unroll
        for (int g = 0; g < 6; g++)
            #pragma unroll
            for (int p = 0; p < 4; p++) acc[g][p] = binit[p];

        #pragma unroll 1
        for (int b = 0; b < 7; b++) {
            const float* qa = QsA + b * (HWN * 4);
            const float* qb = QsB + b * (HWN * 4);
            const ull*   bp = basP + b * 108 + gh * 6;   // b*9*12
            #pragma unroll
            for (int uv = 0; uv < 9; uv++) {
                int u = uv / 3, vv = uv - u * 3;
                int pos = pbase + u * 40 + vv;
                ulonglong2 qA = *(const ulonglong2*)(qa + pos * 4);  // o(0,1),(2,3)
                ulonglong2 qB = *(const ulonglong2*)(qb + pos * 4);  // o(4,5),(6,7)
                const ull* bk = bp + uv * 12;
                #pragma unroll
                for (int g = 0; g < 6; g++) {
                    ull bv = bk[g];      // LDS.64 broadcast (pre-duplicated)
                    acc[g][0] = fma2(qA.x, bv, acc[g][0]);
                    acc[g][1] = fma2(qA.y, bv, acc[g][1]);
                    acc[g][2] = fma2(qB.x, bv, acc[g][2]);
                    acc[g][3] = fma2(qB.y, bv, acc[g][3]);
                }
            }
        }
        // Group t lands at output g = t (interior) or (t+11)%12 (border).
        #pragma unroll
        for (int g = 0; g < 6; g++) {
            int t = gh * 6 + g;
            int gout = border ? (t == 0 ? 11 : t - 1) : t;
            float* ob8 = obase + (size_t)(gout * 8) * OSTRIDE;
            #pragma unroll
            for (int p = 0; p < 4; p++) {
                float lo, hi; unpack2(acc[g][p], lo, hi);
                ob8[(size_t)(2 * p)     * OSTRIDE] = lo;
                ob8[(size_t)(2 * p + 1) * OSTRIDE] = hi;
            }
        }
    }
}

// ---------------------------------------------------------------------------
extern "C" void kernel_launch(void* const* d_in, const int* in_sizes, int n_in,
                              void* d_out, int out_size)
{
    const float* x      = (const float*)d_in[0];
    const float* weight = (const float*)d_in[1];
    const float* bias   = (const float*)d_in[2];
    const float* basis  = (const float*)d_in[3];
    const int*   I      = (const int*)d_in[4];
    const int*   J      = (const int*)d_in[5];
    const int*   T      = (const int*)d_in[6];
    float*       out    = (float*)d_out;

    const int smem1 = KKN * WSTRIDE * 4 + (KKN + 2) * 4;          // ~56.2 KB
    const int smem2 = 756 * 8 + (QTILE + 8) * 4;                  // ~77.8 KB
    cudaFuncSetAttribute(stage1_kernel, cudaFuncAttributeMaxDynamicSharedMemorySize, smem1);
    cudaFuncSetAttribute(stage2_kernel, cudaFuncAttributeMaxDynamicSharedMemorySize, smem2);

    stage1_kernel<<<NB, 320, smem1>>>(x, weight);
    stage2_kernel<<<VOX, 320, smem2>>>(bias, basis, I, J, T, out);
}

// round 15
// speedup vs baseline: 1.1544x; 1.0107x over previous
#include <cuda_runtime.h>

// Problem constants (fixed by the reference):
// B=1, C=8, O=8, G=12, X=12, CH=8, CW=40, Xo=Yo=Zo=9
#define HWN   320      // CH*CW
#define NB    729      // 9*9*9 interior voxels
#define OBN   56       // O*7  (ob = o*7+b)
#define KKN   216      // C*27
#define KPN   108      // k-pairs
#define GON   96       // G*O
#define VOX   1728     // 12*12*12
#define OSTRIDE (VOX*HWN)         // 552960, stride of one (g,o) plane
#define QHALF (7*HWN*4)           // 8960 floats: one o-half plane per n
#define QTILE (2*QHALF)           // 17920 floats per n
#define WP_STRIDE 128             // floats per k-pair row in w_s (112 used, padded)

typedef unsigned long long ull;

__device__ __forceinline__ ull fma2(ull a, ull b, ull c) {
    ull d; asm("fma.rn.f32x2 %0, %1, %2, %3;" : "=l"(d) : "l"(a), "l"(b), "l"(c)); return d;
}
__device__ __forceinline__ ull pack2(float lo, float hi) {
    ull d; asm("mov.b64 %0, {%1, %2};" : "=l"(d) : "f"(lo), "f"(hi)); return d;
}
__device__ __forceinline__ void unpack2(ull v, float& lo, float& hi) {
    asm("mov.b64 {%0, %1}, %2;" : "=f"(lo), "=f"(hi) : "l"(v));
}

// Scratch: per n, two split planes:
//   QA[n][b*320+hw][o0..3] at offset 0, QB[n][b*320+hw][o4..7] at offset QHALF.
// 16-B pos stride so stage2 tap reads are conflict-free LDS.128.
__device__ __align__(16) float g_Q[NB * QTILE];

// ---------------------------------------------------------------------------
// Stage 1: register-tiled GEMM  Q[ob, hw] = sum_k W[ob,k] * X[k, hw]  per n.
// Thread shape: 28 ob x 2 hw. Block 320 = obh(2) x hwp(160); warp-uniform obh.
// k-PAIRED W layout: one LDS.128 = {w[k0][ob],w[k0][ob+1],w[k1][ob],w[k1][ob+1]}
// -> per 2 k: 7 LDS.128 (bcast) + 2 LDG.64 (x) + 56 FFMA2.
// ---------------------------------------------------------------------------
extern "C" __global__ void __launch_bounds__(320, 2)
stage1_kernel(const float* __restrict__ x, const float* __restrict__ weight)
{
    extern __shared__ float sm1[];
    float* w_s    = sm1;                            // KPN*WP_STRIDE floats
    int*   rowoff = (int*)(w_s + KPN * WP_STRIDE);  // KKN+4 ints

    const int n   = blockIdx.x;
    const int tid = threadIdx.x;

    // weight[o][c][f][b] -> w_s[(k/2)*128 + obh*56 + (obl/2)*4 + (k%2)*2 + obl%2]
    for (int idx = tid; idx < KKN * OBN; idx += 320) {
        int k = idx / OBN, ob = idx % OBN;
        int c = k / 27,    f  = k % 27;
        int o = ob / 7,    b  = ob % 7;
        int obh = ob / 28, obl = ob % 28;
        int j = obl >> 1,  lo = obl & 1;
        int kp = k >> 1,   kl = k & 1;
        w_s[kp * WP_STRIDE + obh * 56 + j * 4 + kl * 2 + lo] =
            weight[((o * 8 + c) * 27 + f) * 7 + b];
    }
    const int xi = n / 81, yj = (n / 9) % 9, zk = n % 9;
    for (int k = tid; k < KKN + 4; k += 320) {
        int kc = (k < KKN) ? k : (KKN - 1);
        int c = kc / 27, f = kc % 27;
        int fi = f / 9, fj = (f / 3) % 3, fk = f % 3;
        rowoff[k] = (((c * 12 + xi + fi) * 12 + (yj + fj)) * 12 + (zk + fk)) * HWN;
    }
    __syncthreads();

    const int obh = tid / 160;         // 0/1, uniform per warp (160 = 5 warps)
    const int hwb = (tid % 160) * 2;   // hw base, warp = 256B contiguous LDG.64

    ull acc[14][2];                    // [ob-pair j][hw p]
    #pragma unroll
    for (int j = 0; j < 14; j++) { acc[j][0] = 0ULL; acc[j][1] = 0ULL; }

    float2 p0 = __ldg((const float2*)(x + rowoff[0] + hwb));
    float2 p1 = __ldg((const float2*)(x + rowoff[1] + hwb));
    float2 p2 = __ldg((const float2*)(x + rowoff[2] + hwb));
    float2 p3 = __ldg((const float2*)(x + rowoff[3] + hwb));
    for (int kp = 0; kp < KPN; kp++) {
        float2 pn0 = __ldg((const float2*)(x + rowoff[2 * kp + 4] + hwb));
        float2 pn1 = __ldg((const float2*)(x + rowoff[2 * kp + 5] + hwb));
        ull a0 = pack2(p0.x, p0.x), a1 = pack2(p0.y, p0.y);   // k0
        ull b0 = pack2(p1.x, p1.x), b1 = pack2(p1.y, p1.y);   // k1
        const ulonglong2* wp = (const ulonglong2*)(w_s + kp * WP_STRIDE + obh * 56);
        #pragma unroll
        for (int j = 0; j < 14; j++) {
            ulonglong2 w4 = wp[j];     // .x = k0 ob-pair, .y = k1 ob-pair
            acc[j][0] = fma2(w4.x, a0, acc[j][0]);
            acc[j][1] = fma2(w4.x, a1, acc[j][1]);
            acc[j][0] = fma2(w4.y, b0, acc[j][0]);
            acc[j][1] = fma2(w4.y, b1, acc[j][1]);
        }
        p0 = p2; p1 = p3; p2 = pn0; p3 = pn1;
    }

    float accf[28][2];
    #pragma unroll
    for (int j = 0; j < 14; j++) {
        unpack2(acc[j][0], accf[2 * j][0], accf[2 * j + 1][0]);
        unpack2(acc[j][1], accf[2 * j][1], accf[2 * j + 1][1]);
    }

    // Store split: half obh -> plane at obh*QHALF, [(b*320+hw)*4 + ol].
    float* qn = g_Q + (size_t)n * QTILE + obh * QHALF;
    #pragma unroll
    for (int b = 0; b < 7; b++) {
        #pragma unroll
        for (int p = 0; p < 2; p++) {
            float4 v = make_float4(accf[b][p], accf[7 + b][p],
                                   accf[14 + b][p], accf[21 + b][p]);
            *reinterpret_cast<float4*>(qn + (b * HWN + hwb + p) * 4) = v;
        }
    }
}

// ---------------------------------------------------------------------------
// Stage 2 (direct-write + border zero): one block per output voxel.
// Border voxels: zero the 96x320 slab. Interior: thread = hw; compute the
// full 12g x 8o stack at clamped (ii,jj); T-gather is a static output-index
// rotation (T[g] = g interior, (g+1)%12 border); bias index = o.
// Q taps: two conflict-free LDS.128; basis: 3 paired LDS.128 per (b,uv).
// ---------------------------------------------------------------------------
extern "C" __global__ void __launch_bounds__(320, 2)
stage2_kernel(const float* __restrict__ bias,
              const float* __restrict__ basis,
              const int*   __restrict__ Iin,
              const int*   __restrict__ Jin,
              const int*   __restrict__ Tin,
              float*       __restrict__ out)
{
    extern __shared__ char sm2raw[];
    ull*   basP = (ull*)sm2raw;                  // [k=63][g=12] duplicated pairs
    float* QsA  = (float*)(basP + 756);          // 8960 floats (o0..3)
    float* QsB  = QsA + QHALF;                   // 8960 floats (o4..7)
    float* bsum = QsB + QHALF;                   // 8

    const int v   = blockIdx.x;                  // voxel 0..1727
    const int tid = threadIdx.x;
    const int xx = v / 144, yy = (v / 12) % 12, zz = v % 12;
    const bool interior = (xx >= 1 && xx <= 9 && yy >= 1 && yy <= 9 && zz >= 1 && zz <= 9);

    if (!interior) {
        // Zero the 96 (g,o)-planes of this voxel: coalesced float4.
        float4* out4 = (float4*)out;
        const size_t base4 = (size_t)v * (HWN / 4);
        for (int i = tid; i < GON * (HWN / 4); i += 320) {
            int go = i / (HWN / 4), q = i % (HWN / 4);
            out4[(size_t)go * (OSTRIDE / 4) + base4 + q] = make_float4(0.f, 0.f, 0.f, 0.f);
        }
        return;
    }

    const int n = (xx - 1) * 81 + (yy - 1) * 9 + (zz - 1);

    {
        const float4* src = (const float4*)(g_Q + (size_t)n * QTILE);
        float4* dst = (float4*)QsA;   // QsA and QsB are contiguous
        for (int i = tid; i < QTILE / 4; i += 320) dst[i] = src[i];
    }
    // basis[g][b][u][v] -> basP[(b*9+uv)*12 + g], duplicated into both halves.
    for (int i = tid; i < 756; i += 320) {
        float val = basis[i];
        int g = i / 63, k = i % 63;
        basP[k * 12 + g] = pack2(val, val);
    }
    if (tid < 8) {
        // bias_basis = tile(arange(O), G) -> bias index is o.
        float s = 0.f;
        for (int i = 0; i < 27; i++) s += bias[tid * 27 + i];
        bsum[tid] = s;
    }
    __syncthreads();

    const int ii = __ldg(Iin + tid) - 1;          // in [0,5]
    const int jj = __ldg(Jin + tid) - 1;          // in [0,37]
    const bool border = (__ldg(Tin + tid) != 0);  // T[g=0]: 1 on border, 0 inside
    const int pbase = ii * 40 + jj;

    ull binit[4];
    #pragma unroll
    for (int p = 0; p < 4; p++) binit[p] = pack2(bsum[2 * p], bsum[2 * p + 1]);

    float* obase = out + (size_t)v * HWN + tid;

    #pragma unroll 1
    for (int gh = 0; gh < 2; gh++) {
        ull acc[6][4];
        #pragma unroll
        for (int g = 0; g < 6; g++)
            #pragma unroll
            for (int p = 0; p < 4; p++) acc[g][p] = binit[p];

        #pragma unroll 1
        for (int b = 0; b < 7; b++) {
            const float* qa = QsA + b * (HWN * 4);
            const float* qb = QsB + b * (HWN * 4);
            const ull*   bp = basP + b * 108 + gh * 6;   // b*9*12
            #pragma unroll
            for (int uv = 0; uv < 9; uv++) {
                int u = uv / 3, vv = uv - u * 3;
                int pos = pbase + u * 40 + vv;
                ulonglong2 qA = *(const ulonglong2*)(qa + pos * 4);  // o(0,1),(2,3)
                ulonglong2 qB = *(const ulonglong2*)(qb + pos * 4);  // o(4,5),(6,7)
                const ulonglong2* bk2 = (const ulonglong2*)(bp + uv * 12);
                #pragma unroll
                for (int gi = 0; gi < 3; gi++) {
                    ulonglong2 bv2 = bk2[gi];   // LDS.128 bcast: g-pair (2gi,2gi+1)
                    acc[2 * gi    ][0] = fma2(qA.x, bv2.x, acc[2 * gi    ][0]);
                    acc[2 * gi    ][1] = fma2(qA.y, bv2.x, acc[2 * gi    ][1]);
                    acc[2 * gi    ][2] = fma2(qB.x, bv2.x, acc[2 * gi    ][2]);
                    acc[2 * gi    ][3] = fma2(qB.y, bv2.x, acc[2 * gi    ][3]);
                    acc[2 * gi + 1][0] = fma2(qA.x, bv2.y, acc[2 * gi + 1][0]);
                    acc[2 * gi + 1][1] = fma2(qA.y, bv2.y, acc[2 * gi + 1][1]);
                    acc[2 * gi + 1][2] = fma2(qB.x, bv2.y, acc[2 * gi + 1][2]);
                    acc[2 * gi + 1][3] = fma2(qB.y, bv2.y, acc[2 * gi + 1][3]);
                }
            }
        }
        // Group t lands at output g = t (interior) or (t+11)%12 (border).
        #pragma unroll
        for (int g = 0; g < 6; g++) {
            int t = gh * 6 + g;
            int gout = border ? (t == 0 ? 11 : t - 1) : t;
            float* ob8 = obase + (size_t)(gout * 8) * OSTRIDE;
            #pragma unroll
            for (int p = 0; p < 4; p++) {
                float lo, hi; unpack2(acc[g][p], lo, hi);
                ob8[(size_t)(2 * p)     * OSTRIDE] = lo;
                ob8[(size_t)(2 * p + 1) * OSTRIDE] = hi;
            }
        }
    }
}

// ---------------------------------------------------------------------------
extern "C" void kernel_launch(void* const* d_in, const int* in_sizes, int n_in,
                              void* d_out, int out_size)
{
    const float* x      = (const float*)d_in[0];
    const float* weight = (const float*)d_in[1];
    const float* bias   = (const float*)d_in[2];
    const float* basis  = (const float*)d_in[3];
    const int*   I      = (const int*)d_in[4];
    const int*   J      = (const int*)d_in[5];
    const int*   T      = (const int*)d_in[6];
    float*       out    = (float*)d_out;

    const int smem1 = KPN * WP_STRIDE * 4 + (KKN + 4) * 4;        // ~56.2 KB
    const int smem2 = 756 * 8 + (QTILE + 8) * 4;                  // ~77.8 KB
    cudaFuncSetAttribute(stage1_kernel, cudaFuncAttributeMaxDynamicSharedMemorySize, smem1);
    cudaFuncSetAttribute(stage2_kernel, cudaFuncAttributeMaxDynamicSharedMemorySize, smem2);

    stage1_kernel<<<NB, 320, smem1>>>(x, weight);
    stage2_kernel<<<VOX, 320, smem2>>>(bias, basis, I, J, T, out);
}

// round 16
// speedup vs baseline: 1.2273x; 1.0631x over previous
#include <cuda_runtime.h>

// Problem constants (fixed by the reference):
// B=1, C=8, O=8, G=12, X=12, CH=8, CW=40, Xo=Yo=Zo=9
#define HWN   320      // CH*CW
#define NB    729      // 9*9*9 interior voxels
#define KKN   216      // C*27
#define KPN   108      // k-pairs
#define GON   96       // G*O
#define VOX   1728     // 12*12*12
#define OSTRIDE (VOX*HWN)         // 552960, stride of one (g,o) plane
#define QHALF (7*HWN*4)           // 8960 floats: one o-half plane per n
#define QTILE (2*QHALF)           // 17920 floats per n

typedef unsigned long long ull;

__device__ __forceinline__ ull fma2(ull a, ull b, ull c) {
    ull d; asm("fma.rn.f32x2 %0, %1, %2, %3;" : "=l"(d) : "l"(a), "l"(b), "l"(c)); return d;
}
__device__ __forceinline__ ull pack2(float lo, float hi) {
    ull d; asm("mov.b64 %0, {%1, %2};" : "=l"(d) : "f"(lo), "f"(hi)); return d;
}
__device__ __forceinline__ void unpack2(ull v, float& lo, float& hi) {
    asm("mov.b64 {%0, %1}, %2;" : "=f"(lo), "=f"(hi) : "l"(v));
}

// Scratch: per n, two split planes:
//   QA[n][(b*320+hw)*4 + o0..3] at 0, QB[...o4..7] at QHALF.
// 16-B pos stride so stage2 tap reads are conflict-free LDS.128.
__device__ __align__(16) float g_Q[NB * QTILE];

// ---------------------------------------------------------------------------
// Stage 1: register-tiled GEMM  Q[ob, hw] = sum_k W[ob,k] * X[k, hw].
// Grid 1458 = n (729) x ob-half (2: obs [28h, 28h+28)).  Block 320 =
// obq(2, warp-uniform) x 160 hw-groups; thread = 14 ob x 2 hw (acc 28 regs).
// k-paired W: one LDS.128 = {w[k0][ob0],w[k0][ob1],w[k1][ob0],w[k1][ob1]}
// -> per 2 k: 7 LDS.128 (bcast) + 2 LDG.64 (x) + 28 FFMA2.
// 3 CTAs/SM (68 regs, 25.1 KB static smem) -> 30 warps/SM.
// ---------------------------------------------------------------------------
extern "C" __global__ void __launch_bounds__(320, 3)
stage1_kernel(const float* __restrict__ x, const float* __restrict__ weight)
{
    __shared__ float w_s[KPN * 56];        // 6048 floats, this half's 28 obs
    __shared__ int   rowoff[KKN + 4];

    const int bid  = blockIdx.x;
    const int n    = bid >> 1;
    const int half = bid & 1;
    const int tid  = threadIdx.x;

    // weight[o][c][f][b] -> w_s[kp*56 + q*28 + (oblq/2)*4 + (k%2)*2 + oblq%2]
    for (int idx = tid; idx < KKN * 28; idx += 320) {
        int k   = idx / 28, obl = idx - k * 28;       // obl local 0..27
        int ob  = half * 28 + obl;
        int o   = ob / 7,  b = ob - o * 7;
        int c   = k / 27,  f = k - c * 27;
        int q   = obl / 14, oblq = obl - q * 14;
        int kp  = k >> 1,   kl = k & 1;
        w_s[kp * 56 + q * 28 + (oblq >> 1) * 4 + kl * 2 + (oblq & 1)] =
            weight[((o * 8 + c) * 27 + f) * 7 + b];
    }
    const int xi = n / 81, yj = (n / 9) % 9, zk = n % 9;
    for (int k = tid; k < KKN + 4; k += 320) {
        int kc = (k < KKN) ? k : (KKN - 1);
        int c = kc / 27, f = kc % 27;
        int fi = f / 9, fj = (f / 3) % 3, fk = f % 3;
        rowoff[k] = (((c * 12 + xi + fi) * 12 + (yj + fj)) * 12 + (zk + fk)) * HWN;
    }
    __syncthreads();

    const int obq = tid / 160;         // 0/1, uniform per warp (160 = 5 warps)
    const int hwb = (tid % 160) * 2;   // hw base; warp = 256B contiguous LDG.64

    ull acc[7][2];                     // [ob-pair j][hw p]
    #pragma unroll
    for (int j = 0; j < 7; j++) { acc[j][0] = 0ULL; acc[j][1] = 0ULL; }

    float2 p0 = __ldg((const float2*)(x + rowoff[0] + hwb));
    float2 p1 = __ldg((const float2*)(x + rowoff[1] + hwb));
    float2 p2 = __ldg((const float2*)(x + rowoff[2] + hwb));
    float2 p3 = __ldg((const float2*)(x + rowoff[3] + hwb));
    for (int kp = 0; kp < KPN; kp++) {
        float2 pn0 = __ldg((const float2*)(x + rowoff[2 * kp + 4] + hwb));
        float2 pn1 = __ldg((const float2*)(x + rowoff[2 * kp + 5] + hwb));
        ull a0 = pack2(p0.x, p0.x), a1 = pack2(p0.y, p0.y);   // k0
        ull b0 = pack2(p1.x, p1.x), b1 = pack2(p1.y, p1.y);   // k1
        const ulonglong2* wp = (const ulonglong2*)(w_s + kp * 56 + obq * 28);
        #pragma unroll
        for (int j = 0; j < 7; j++) {
            ulonglong2 w4 = wp[j];     // .x = k0 ob-pair, .y = k1 ob-pair
            acc[j][0] = fma2(w4.x, a0, acc[j][0]);
            acc[j][1] = fma2(w4.x, a1, acc[j][1]);
            acc[j][0] = fma2(w4.y, b0, acc[j][0]);
            acc[j][1] = fma2(w4.y, b1, acc[j][1]);
        }
        p0 = p2; p1 = p3; p2 = pn0; p3 = pn1;
    }

    float accf[14][2];
    #pragma unroll
    for (int j = 0; j < 7; j++) {
        unpack2(acc[j][0], accf[2 * j][0], accf[2 * j + 1][0]);
        unpack2(acc[j][1], accf[2 * j][1], accf[2 * j + 1][1]);
    }

    // Store: plane = half (QA/QB); float2 of (o_loc0,o_loc1) at ol = obq*2.
    float* qn = g_Q + (size_t)n * QTILE + half * QHALF + obq * 2;
    #pragma unroll
    for (int b = 0; b < 7; b++) {
        #pragma unroll
        for (int p = 0; p < 2; p++) {
            float2 v = make_float2(accf[b][p], accf[7 + b][p]);
            *reinterpret_cast<float2*>(qn + (b * HWN + hwb + p) * 4) = v;
        }
    }
}

// ---------------------------------------------------------------------------
// Stage 2 (direct-write + border zero): grid 3456 = voxel (1728) x o-half (2).
// Border: zero this half's 48 (g,o)-planes. Interior: thread = hw; 12g x 4o
// stack at clamped (ii,jj); T-gather is a static output-index rotation
// (T[g] = g interior, (g+1)%12 border); bias index = o folds into acc init.
// 3 CTAs/SM (41.9 KB static smem, 68 regs) -> 30 warps/SM.
// ---------------------------------------------------------------------------
extern "C" __global__ void __launch_bounds__(320, 3)
stage2_kernel(const float* __restrict__ bias,
              const float* __restrict__ basis,
              const int*   __restrict__ Iin,
              const int*   __restrict__ Jin,
              const int*   __restrict__ Tin,
              float*       __restrict__ out)
{
    __shared__ ull   basP[756];        // [k=63][g=12] duplicated pairs
    __shared__ float Qs[QHALF];        // 8960 floats (this o-half)
    __shared__ float bsum[8];

    const int bid = blockIdx.x;
    const int v   = bid >> 1;          // voxel 0..1727
    const int oh  = bid & 1;           // o-half: o in [4*oh, 4*oh+4)
    const int tid = threadIdx.x;
    const int xx = v / 144, yy = (v / 12) % 12, zz = v % 12;
    const bool interior = (xx >= 1 && xx <= 9 && yy >= 1 && yy <= 9 && zz >= 1 && zz <= 9);

    if (!interior) {
        // Zero this half's 48 (g,o)-planes of this voxel: coalesced float4.
        float4* out4 = (float4*)out;
        const size_t base4 = (size_t)v * (HWN / 4);
        for (int i = tid; i < 48 * (HWN / 4); i += 320) {
            int goh = i / (HWN / 4), q = i % (HWN / 4);
            int g = goh >> 2, ol = goh & 3;
            out4[(size_t)(g * 8 + oh * 4 + ol) * (OSTRIDE / 4) + base4 + q] =
                make_float4(0.f, 0.f, 0.f, 0.f);
        }
        return;
    }

    const int n = (xx - 1) * 81 + (yy - 1) * 9 + (zz - 1);

    {
        const float4* src = (const float4*)(g_Q + (size_t)n * QTILE + oh * QHALF);
        float4* dst = (float4*)Qs;
        for (int i = tid; i < QHALF / 4; i += 320) dst[i] = src[i];
    }
    // basis[g][b][u][v] -> basP[(b*9+uv)*12 + g], duplicated into both halves.
    for (int i = tid; i < 756; i += 320) {
        float val = basis[i];
        int g = i / 63, k = i % 63;
        basP[k * 12 + g] = pack2(val, val);
    }
    if (tid < 8) {
        // bias_basis = tile(arange(O), G) -> bias index is o.
        float s = 0.f;
        for (int i = 0; i < 27; i++) s += bias[tid * 27 + i];
        bsum[tid] = s;
    }
    __syncthreads();

    const int ii = __ldg(Iin + tid) - 1;          // in [0,5]
    const int jj = __ldg(Jin + tid) - 1;          // in [0,37]
    const bool border = (__ldg(Tin + tid) != 0);  // T[g=0]: 1 on border, 0 inside
    const int pbase = ii * 40 + jj;

    ull binit[2];
    #pragma unroll
    for (int p = 0; p < 2; p++) binit[p] = pack2(bsum[oh * 4 + 2 * p], bsum[oh * 4 + 2 * p + 1]);

    float* obase = out + (size_t)v * HWN + tid;

    #pragma unroll 1
    for (int gh = 0; gh < 2; gh++) {
        ull acc[6][2];
        #pragma unroll
        for (int g = 0; g < 6; g++) { acc[g][0] = binit[0]; acc[g][1] = binit[1]; }

        #pragma unroll 1
        for (int b = 0; b < 7; b++) {
            const float* qa = Qs + b * (HWN * 4);
            const ull*   bp = basP + b * 108 + gh * 6;   // b*9*12
            #pragma unroll
            for (int uv = 0; uv < 9; uv++) {
                int u = uv / 3, vv = uv - u * 3;
                int pos = pbase + u * 40 + vv;
                ulonglong2 qA = *(const ulonglong2*)(qa + pos * 4);  // o-pairs of half
                const ulonglong2* bk2 = (const ulonglong2*)(bp + uv * 12);
                #pragma unroll
                for (int gi = 0; gi < 3; gi++) {
                    ulonglong2 bv2 = bk2[gi];   // LDS.128 bcast: g-pair (2gi,2gi+1)
                    acc[2 * gi    ][0] = fma2(qA.x, bv2.x, acc[2 * gi    ][0]);
                    acc[2 * gi    ][1] = fma2(qA.y, bv2.x, acc[2 * gi    ][1]);
                    acc[2 * gi + 1][0] = fma2(qA.x, bv2.y, acc[2 * gi + 1][0]);
                    acc[2 * gi + 1][1] = fma2(qA.y, bv2.y, acc[2 * gi + 1][1]);
                }
            }
        }
        // Group t lands at output g = t (interior) or (t+11)%12 (border).
        #pragma unroll
        for (int g = 0; g < 6; g++) {
            int t = gh * 6 + g;
            int gout = border ? (t == 0 ? 11 : t - 1) : t;
            float* ob8 = obase + (size_t)(gout * 8 + oh * 4) * OSTRIDE;
            #pragma unroll
            for (int p = 0; p < 2; p++) {
                float lo, hi; unpack2(acc[g][p], lo, hi);
                ob8[(size_t)(2 * p)     * OSTRIDE] = lo;
                ob8[(size_t)(2 * p + 1) * OSTRIDE] = hi;
            }
        }
    }
}

// ---------------------------------------------------------------------------
extern "C" void kernel_launch(void* const* d_in, const int* in_sizes, int n_in,
                              void* d_out, int out_size)
{
    const float* x      = (const float*)d_in[0];
    const float* weight = (const float*)d_in[1];
    const float* bias   = (const float*)d_in[2];
    const float* basis  = (const float*)d_in[3];
    const int*   I      = (const int*)d_in[4];
    const int*   J      = (const int*)d_in[5];
    const int*   T      = (const int*)d_in[6];
    float*       out    = (float*)d_out;

    stage1_kernel<<<2 * NB, 320>>>(x, weight);
    stage2_kernel<<<2 * VOX, 320>>>(bias, basis, I, J, T, out);
}